// round 8
// baseline (speedup 1.0000x reference)
#include <cuda_runtime.h>
#include <cuda_bf16.h>
#include <cstdint>

#define N_NODES 50000
#define N_TILES 391                // ceil(50000/128)
#define N_REL   8
#define N_EDGES 64000
#define D       128
#define NTOT    (N_REL * N_NODES)
#define NBINS   (N_REL * N_TILES)  // 3128

// -------- scratch (static device globals; no runtime allocation) ----------
__device__ __align__(16) float   g_odeg[NTOT];            // raw counts
__device__ __align__(16) float   g_ideg[NTOT];            // raw counts
__device__ __align__(16) uint8_t g_ft_hi[(size_t)N_TILES * 32768];
__device__ __align__(16) uint8_t g_ft_lo[(size_t)N_TILES * 32768];
__device__ __align__(16) uint8_t g_wt_hi[N_REL * 32768];
__device__ __align__(16) uint8_t g_wt_lo[N_REL * 32768];
__device__ __align__(16) uint2   g_edges[N_REL * N_EDGES];   // {src7|dst<<7, scale}
__device__ int g_hist[NBINS];
__device__ int g_cur[NBINS];
__device__ int g_off[NBINS + 1];

// -------- helpers -----------------------------------------------------------
__device__ __forceinline__ void red_add_v4(float* p, float4 v) {
    asm volatile("red.global.add.v4.f32 [%0], {%1,%2,%3,%4};"
                 :: "l"(p), "f"(v.x), "f"(v.y), "f"(v.z), "f"(v.w)
                 : "memory");
}
__device__ __forceinline__ uint32_t smem_u32(const void* p) {
    uint32_t a;
    asm("{ .reg .u64 t; cvta.to.shared.u64 t, %1; cvt.u32.u64 %0, t; }"
        : "=r"(a) : "l"(p));
    return a;
}
__device__ __forceinline__ void cp_async16(uint32_t saddr, const void* g) {
    asm volatile("cp.async.cg.shared.global [%0], [%1], 16;"
                 :: "r"(saddr), "l"(g) : "memory");
}
#define CP_COMMIT() asm volatile("cp.async.commit_group;" ::: "memory")
#define CP_WAIT(n)  asm volatile("cp.async.wait_group %0;" :: "n"(n) : "memory")

// image: row-major [128 rows][128 bf16], 16B chunks, c' = c ^ (row&7)
__device__ __forceinline__ uint32_t img_off(int row, int c) {
    return (uint32_t)row * 256u + (uint32_t)((c ^ (row & 7)) << 4);
}
__device__ __forceinline__ void split2(float a, float b, uint32_t& h, uint32_t& l) {
    __nv_bfloat16 ha = __float2bfloat16(a);
    __nv_bfloat16 hb = __float2bfloat16(b);
    __nv_bfloat16 la = __float2bfloat16(a - __bfloat162float(ha));
    __nv_bfloat16 lb = __float2bfloat16(b - __bfloat162float(hb));
    __nv_bfloat162 hp; hp.x = ha; hp.y = hb;
    __nv_bfloat162 lp; lp.x = la; lp.y = lb;
    h = *reinterpret_cast<uint32_t*>(&hp);
    l = *reinterpret_cast<uint32_t*>(&lp);
}
__device__ __forceinline__ void ldsm_x4(uint32_t addr, uint32_t& r0, uint32_t& r1,
                                        uint32_t& r2, uint32_t& r3) {
    asm volatile("ldmatrix.sync.aligned.m8n8.x4.shared.b16 {%0,%1,%2,%3}, [%4];"
                 : "=r"(r0), "=r"(r1), "=r"(r2), "=r"(r3) : "r"(addr));
}
__device__ __forceinline__ void mma_bf16(float& d0, float& d1, float& d2, float& d3,
                                         uint32_t a0, uint32_t a1, uint32_t a2,
                                         uint32_t a3, uint32_t b0, uint32_t b1) {
    asm volatile("mma.sync.aligned.m16n8k16.row.col.f32.bf16.bf16.f32 "
                 "{%0,%1,%2,%3}, {%4,%5,%6,%7}, {%8,%9}, {%0,%1,%2,%3};"
                 : "+f"(d0), "+f"(d1), "+f"(d2), "+f"(d3)
                 : "r"(a0), "r"(a1), "r"(a2), "r"(a3), "r"(b0), "r"(b1));
}

// -------- kernel 1: prep (feat images + W images) ---------------------------
__global__ void prep_kernel(const float* __restrict__ feat,
                            const float* __restrict__ W) {
    int bi = blockIdx.x;
    int t  = threadIdx.x;
    if (bi < N_TILES) {
        int row0 = bi * 128;
        #pragma unroll
        for (int i = 0; i < 8; i++) {
            int f   = t + 256 * i;
            int rr  = f >> 4;
            int seg = f & 15;
            int row = row0 + rr;
            float v[8];
            if (row < N_NODES) {
                float4 x0 = ((const float4*)feat)[(size_t)row * 32 + seg * 2];
                float4 x1 = ((const float4*)feat)[(size_t)row * 32 + seg * 2 + 1];
                v[0] = x0.x; v[1] = x0.y; v[2] = x0.z; v[3] = x0.w;
                v[4] = x1.x; v[5] = x1.y; v[6] = x1.z; v[7] = x1.w;
            } else {
                #pragma unroll
                for (int j = 0; j < 8; j++) v[j] = 0.f;
            }
            uint4 hi, lo;
            split2(v[0], v[1], hi.x, lo.x);
            split2(v[2], v[3], hi.y, lo.y);
            split2(v[4], v[5], hi.z, lo.z);
            split2(v[6], v[7], hi.w, lo.w);
            uint32_t off = img_off(rr, seg);
            *(uint4*)(g_ft_hi + (size_t)bi * 32768 + off) = hi;
            *(uint4*)(g_ft_lo + (size_t)bi * 32768 + off) = lo;
        }
    } else {
        int r = bi - N_TILES;
        const float* Wr = W + (size_t)r * D * D;
        int n = t & 127;
        #pragma unroll
        for (int i = 0; i < 8; i++) {
            int seg = (t >> 7) + 2 * i;
            float v[8];
            #pragma unroll
            for (int j = 0; j < 8; j++)
                v[j] = Wr[(seg * 8 + j) * D + n];
            uint4 hi, lo;
            split2(v[0], v[1], hi.x, lo.x);
            split2(v[2], v[3], hi.y, lo.y);
            split2(v[4], v[5], hi.z, lo.z);
            split2(v[6], v[7], hi.w, lo.w);
            uint32_t off = img_off(n, seg);
            *(uint4*)(g_wt_hi + r * 32768 + off) = hi;
            *(uint4*)(g_wt_lo + r * 32768 + off) = lo;
        }
    }
}

// -------- kernel 2: init (out = sum_r b_r; zero degrees + hist) ------------
__global__ void init_kernel(const float* __restrict__ b, float* __restrict__ out) {
    int i = blockIdx.x * blockDim.x + threadIdx.x;
    if (i < N_NODES * D / 4) {
        int c = (i & 31) * 4;
        float4 v = make_float4(0.f, 0.f, 0.f, 0.f);
        #pragma unroll
        for (int r = 0; r < N_REL; r++) {
            v.x += b[r * D + c];     v.y += b[r * D + c + 1];
            v.z += b[r * D + c + 2]; v.w += b[r * D + c + 3];
        }
        ((float4*)out)[i] = v;
    }
    if (i < NTOT / 4) {
        float4 z = make_float4(0.f, 0.f, 0.f, 0.f);
        ((float4*)g_odeg)[i] = z;
        ((float4*)g_ideg)[i] = z;
    }
    if (i < NBINS) g_hist[i] = 0;
}

// -------- kernel 3: degrees + src-tile histogram ----------------------------
__global__ void degree_kernel(const int* __restrict__ src,
                              const int* __restrict__ dst) {
    int e = blockIdx.x * blockDim.x + threadIdx.x;
    int r = blockIdx.y;
    if (e < N_EDGES) {
        int s = src[r * N_EDGES + e];
        int d = dst[r * N_EDGES + e];
        atomicAdd(&g_odeg[r * N_NODES + s], 1.0f);
        atomicAdd(&g_ideg[r * N_NODES + d], 1.0f);
        atomicAdd(&g_hist[r * N_TILES + (s >> 7)], 1);
    }
}

// -------- kernel 4: exclusive scan of 3128 bins (single block) --------------
__global__ void scan_kernel() {
    __shared__ int warp_sums[32];
    int t = threadIdx.x;                  // 1024 threads
    int lane = t & 31, wid = t >> 5;
    int base = t * 4;
    int v[4], s = 0;
    #pragma unroll
    for (int j = 0; j < 4; j++) {
        v[j] = (base + j < NBINS) ? g_hist[base + j] : 0;
        s += v[j];
    }
    int x = s;
    #pragma unroll
    for (int o = 1; o < 32; o <<= 1) {
        int y = __shfl_up_sync(0xFFFFFFFF, x, o);
        if (lane >= o) x += y;
    }
    if (lane == 31) warp_sums[wid] = x;
    __syncthreads();
    if (wid == 0) {
        int y = warp_sums[lane];
        #pragma unroll
        for (int o = 1; o < 32; o <<= 1) {
            int z = __shfl_up_sync(0xFFFFFFFF, y, o);
            if (lane >= o) y += z;
        }
        warp_sums[lane] = y;
    }
    __syncthreads();
    int run = x - s + (wid > 0 ? warp_sums[wid - 1] : 0);   // exclusive prefix
    #pragma unroll
    for (int j = 0; j < 4; j++) {
        if (base + j < NBINS) {
            g_off[base + j] = run;
            g_cur[base + j] = run;
        }
        run += v[j];
    }
    if (t == 1023) g_off[NBINS] = run;    // total = 512000
}

// -------- kernel 5: fill sorted edge records --------------------------------
__global__ void fill_kernel(const int* __restrict__ src,
                            const int* __restrict__ dst) {
    int e = blockIdx.x * blockDim.x + threadIdx.x;
    int r = blockIdx.y;
    if (e >= N_EDGES) return;
    int s = src[r * N_EDGES + e];
    int d = dst[r * N_EDGES + e];
    float sc = rsqrtf(fmaxf(g_odeg[r * N_NODES + s], 1.0f))
             * rsqrtf(fmaxf(g_ideg[r * N_NODES + d], 1.0f));
    int bin = r * N_TILES + (s >> 7);
    int pos = atomicAdd(&g_cur[bin], 1);
    g_edges[pos] = make_uint2((uint32_t)(s & 127) | ((uint32_t)d << 7),
                              __float_as_uint(sc));
}

// -------- kernel 6: fused GEMM + edge scatter -------------------------------
#define OFF_A_HI  0
#define OFF_A_LO  32768
#define OFF_W_HI  65536
#define OFF_W_LO  98304
#define OFF_Y     131072
#define YSTRIDE   132                 // floats; 528 B rows, 16B-aligned, no LDS conflicts
#define GEMM_SMEM (131072 + 128 * YSTRIDE * 4)   // 198656 B

__global__ void __launch_bounds__(256, 1)
gemm_fused_kernel(float* __restrict__ out) {
    extern __shared__ char smem[];
    uint32_t sb = smem_u32(smem);
    float* Ysm = (float*)(smem + OFF_Y);
    int t = threadIdx.x, wid = t >> 5, lane = t & 31;
    int ti = blockIdx.x;
    int row0 = ti * 128;

    int mw0 = (wid >> 2) * 64;
    int nw0 = (wid & 3) * 32;
    int lrow = lane & 15;
    int ksel = lane >> 4;

    // stage A + W_0 (one group)
    {
        const uint8_t* ah = g_ft_hi + (size_t)ti * 32768;
        const uint8_t* al = g_ft_lo + (size_t)ti * 32768;
        #pragma unroll
        for (int i = 0; i < 8; i++) {
            uint32_t o = (uint32_t)(t + 256 * i) * 16;
            cp_async16(sb + OFF_A_HI + o, ah + o);
            cp_async16(sb + OFF_A_LO + o, al + o);
            cp_async16(sb + OFF_W_HI + o, g_wt_hi + o);
            cp_async16(sb + OFF_W_LO + o, g_wt_lo + o);
        }
    }
    CP_COMMIT();
    CP_WAIT(0);
    __syncthreads();

    for (int r = 0; r < N_REL; r++) {
        // ---- MMA phase ----
        float acc[4][4][4];
        #pragma unroll
        for (int mi = 0; mi < 4; mi++)
            #pragma unroll
            for (int ni = 0; ni < 4; ni++)
                #pragma unroll
                for (int q = 0; q < 4; q++) acc[mi][ni][q] = 0.f;

        #pragma unroll
        for (int ks = 0; ks < 8; ks++) {
            int kc = ks * 2 + ksel;
            uint32_t ah[4][4], al[4][4];
            #pragma unroll
            for (int mi = 0; mi < 4; mi++) {
                uint32_t off = img_off(mw0 + mi * 16 + lrow, kc);
                ldsm_x4(sb + OFF_A_HI + off, ah[mi][0], ah[mi][1], ah[mi][2], ah[mi][3]);
                ldsm_x4(sb + OFF_A_LO + off, al[mi][0], al[mi][1], al[mi][2], al[mi][3]);
            }
            uint32_t bh[4][2], bl[4][2];
            #pragma unroll
            for (int nh = 0; nh < 2; nh++) {
                uint32_t off = img_off(nw0 + nh * 16 + lrow, kc);
                uint32_t r0, r1, r2, r3;
                ldsm_x4(sb + OFF_W_HI + off, r0, r1, r2, r3);
                bh[2 * nh][0] = r0; bh[2 * nh + 1][0] = r1;
                bh[2 * nh][1] = r2; bh[2 * nh + 1][1] = r3;
                ldsm_x4(sb + OFF_W_LO + off, r0, r1, r2, r3);
                bl[2 * nh][0] = r0; bl[2 * nh + 1][0] = r1;
                bl[2 * nh][1] = r2; bl[2 * nh + 1][1] = r3;
            }
            #pragma unroll
            for (int mi = 0; mi < 4; mi++)
                #pragma unroll
                for (int ni = 0; ni < 4; ni++) {
                    float* d = acc[mi][ni];
                    mma_bf16(d[0], d[1], d[2], d[3],
                             ah[mi][0], ah[mi][1], ah[mi][2], ah[mi][3],
                             bh[ni][0], bh[ni][1]);
                    mma_bf16(d[0], d[1], d[2], d[3],
                             ah[mi][0], ah[mi][1], ah[mi][2], ah[mi][3],
                             bl[ni][0], bl[ni][1]);
                    mma_bf16(d[0], d[1], d[2], d[3],
                             al[mi][0], al[mi][1], al[mi][2], al[mi][3],
                             bh[ni][0], bh[ni][1]);
                }
        }
        __syncthreads();                 // all warps done reading W

        // ---- prefetch W_{r+1} into the (now dead) W buffer ----
        if (r + 1 < N_REL) {
            const uint8_t* wh = g_wt_hi + (r + 1) * 32768;
            const uint8_t* wl = g_wt_lo + (r + 1) * 32768;
            #pragma unroll
            for (int i = 0; i < 8; i++) {
                uint32_t o = (uint32_t)(t + 256 * i) * 16;
                cp_async16(sb + OFF_W_HI + o, wh + o);
                cp_async16(sb + OFF_W_LO + o, wl + o);
            }
            CP_COMMIT();
        }

        // ---- write Y tile to smem ----
        {
            int qr = lane >> 2;
            int qc = (lane & 3) * 2;
            #pragma unroll
            for (int mi = 0; mi < 4; mi++)
                #pragma unroll
                for (int ni = 0; ni < 4; ni++) {
                    int c  = nw0 + ni * 8 + qc;
                    int ra = mw0 + mi * 16 + qr;
                    *(float2*)(Ysm + ra * YSTRIDE + c) =
                        make_float2(acc[mi][ni][0], acc[mi][ni][1]);
                    *(float2*)(Ysm + (ra + 8) * YSTRIDE + c) =
                        make_float2(acc[mi][ni][2], acc[mi][ni][3]);
                }
        }
        __syncthreads();                 // Y visible to all warps

        // ---- edge phase: scatter this tile's edges for relation r ----
        {
            int bin   = r * N_TILES + ti;
            int start = g_off[bin];
            int end   = g_off[bin + 1];
            for (int i = start + wid; i < end; i += 8) {
                uint2 ed = g_edges[i];
                int   sl = ed.x & 127;
                int   d  = ed.x >> 7;
                float sc = __uint_as_float(ed.y);
                float4 v = *(float4*)(Ysm + sl * YSTRIDE + lane * 4);
                v.x *= sc; v.y *= sc; v.z *= sc; v.w *= sc;
                red_add_v4(&out[(size_t)d * D + lane * 4], v);
            }
        }
        CP_WAIT(0);
        __syncthreads();                 // W_{r+1} ready; Y safe to overwrite
    }
}

// -------- launch -----------------------------------------------------------
extern "C" void kernel_launch(void* const* d_in, const int* in_sizes, int n_in,
                              void* d_out, int out_size) {
    const float* feat = (const float*)d_in[0];   // [50000,128] f32
    const float* W    = (const float*)d_in[1];   // [8,128,128] f32
    const float* b    = (const float*)d_in[2];   // [8,128]     f32
    const int*   src  = (const int*)d_in[3];     // [8,64000]   int32
    const int*   dst  = (const int*)d_in[4];     // [8,64000]   int32
    float* out = (float*)d_out;                  // [50000,128] f32

    cudaFuncSetAttribute(gemm_fused_kernel,
                         cudaFuncAttributeMaxDynamicSharedMemorySize, GEMM_SMEM);

    prep_kernel<<<N_TILES + N_REL, 256>>>(feat, W);          // 1
    init_kernel<<<(N_NODES * D / 4 + 255) / 256, 256>>>(b, out);  // 2
    dim3 egrid(N_EDGES / 256, N_REL);
    degree_kernel<<<egrid, 256>>>(src, dst);                 // 3
    scan_kernel<<<1, 1024>>>();                              // 4
    fill_kernel<<<egrid, 256>>>(src, dst);                   // 5
    gemm_fused_kernel<<<N_TILES, 256, GEMM_SMEM>>>(out);     // 6 (profiled)
}

// round 9
// speedup vs baseline: 1.0058x; 1.0058x over previous
#include <cuda_runtime.h>
#include <cuda_bf16.h>
#include <cstdint>

#define N_NODES 50000
#define N_TILES 391                // ceil(50000/128)
#define N_REL   8
#define N_EDGES 64000
#define D       128
#define NTOT    (N_REL * N_NODES)
#define NBINS   (N_REL * N_TILES)  // 3128

// -------- scratch (static device globals; no runtime allocation) ----------
__device__ __align__(16) float   g_odeg[NTOT];            // raw counts
__device__ __align__(16) float   g_ideg[NTOT];            // raw counts
__device__ __align__(16) uint8_t g_ft_hi[(size_t)N_TILES * 32768];
__device__ __align__(16) uint8_t g_ft_lo[(size_t)N_TILES * 32768];
__device__ __align__(16) uint8_t g_wt_hi[N_REL * 32768];
__device__ __align__(16) uint8_t g_wt_lo[N_REL * 32768];
__device__ __align__(16) uint2   g_edges[N_REL * N_EDGES];   // {src7|dst<<7, scale}
__device__ int g_hist[NBINS];
__device__ int g_cur[NBINS];
__device__ int g_off[NBINS + 1];

// -------- helpers -----------------------------------------------------------
__device__ __forceinline__ void red_add_v4(float* p, float4 v) {
    asm volatile("red.global.add.v4.f32 [%0], {%1,%2,%3,%4};"
                 :: "l"(p), "f"(v.x), "f"(v.y), "f"(v.z), "f"(v.w)
                 : "memory");
}
__device__ __forceinline__ uint32_t smem_u32(const void* p) {
    uint32_t a;
    asm("{ .reg .u64 t; cvta.to.shared.u64 t, %1; cvt.u32.u64 %0, t; }"
        : "=r"(a) : "l"(p));
    return a;
}
__device__ __forceinline__ void cp_async16(uint32_t saddr, const void* g) {
    asm volatile("cp.async.cg.shared.global [%0], [%1], 16;"
                 :: "r"(saddr), "l"(g) : "memory");
}
#define CP_COMMIT() asm volatile("cp.async.commit_group;" ::: "memory")
#define CP_WAIT(n)  asm volatile("cp.async.wait_group %0;" :: "n"(n) : "memory")

// image: row-major [128 rows][128 bf16], 16B chunks, c' = c ^ (row&7)
__device__ __forceinline__ uint32_t img_off(int row, int c) {
    return (uint32_t)row * 256u + (uint32_t)((c ^ (row & 7)) << 4);
}
__device__ __forceinline__ void split2(float a, float b, uint32_t& h, uint32_t& l) {
    __nv_bfloat16 ha = __float2bfloat16(a);
    __nv_bfloat16 hb = __float2bfloat16(b);
    __nv_bfloat16 la = __float2bfloat16(a - __bfloat162float(ha));
    __nv_bfloat16 lb = __float2bfloat16(b - __bfloat162float(hb));
    __nv_bfloat162 hp; hp.x = ha; hp.y = hb;
    __nv_bfloat162 lp; lp.x = la; lp.y = lb;
    h = *reinterpret_cast<uint32_t*>(&hp);
    l = *reinterpret_cast<uint32_t*>(&lp);
}
__device__ __forceinline__ void ldsm_x4(uint32_t addr, uint32_t& r0, uint32_t& r1,
                                        uint32_t& r2, uint32_t& r3) {
    asm volatile("ldmatrix.sync.aligned.m8n8.x4.shared.b16 {%0,%1,%2,%3}, [%4];"
                 : "=r"(r0), "=r"(r1), "=r"(r2), "=r"(r3) : "r"(addr));
}
__device__ __forceinline__ void mma_bf16(float& d0, float& d1, float& d2, float& d3,
                                         uint32_t a0, uint32_t a1, uint32_t a2,
                                         uint32_t a3, uint32_t b0, uint32_t b1) {
    asm volatile("mma.sync.aligned.m16n8k16.row.col.f32.bf16.bf16.f32 "
                 "{%0,%1,%2,%3}, {%4,%5,%6,%7}, {%8,%9}, {%0,%1,%2,%3};"
                 : "+f"(d0), "+f"(d1), "+f"(d2), "+f"(d3)
                 : "r"(a0), "r"(a1), "r"(a2), "r"(a3), "r"(b0), "r"(b1));
}

// -------- kernel 1: prep (feat images + W images) ---------------------------
__global__ void prep_kernel(const float* __restrict__ feat,
                            const float* __restrict__ W) {
    int bi = blockIdx.x;
    int t  = threadIdx.x;
    if (bi < N_TILES) {
        int row0 = bi * 128;
        #pragma unroll
        for (int i = 0; i < 8; i++) {
            int f   = t + 256 * i;
            int rr  = f >> 4;
            int seg = f & 15;
            int row = row0 + rr;
            float v[8];
            if (row < N_NODES) {
                float4 x0 = ((const float4*)feat)[(size_t)row * 32 + seg * 2];
                float4 x1 = ((const float4*)feat)[(size_t)row * 32 + seg * 2 + 1];
                v[0] = x0.x; v[1] = x0.y; v[2] = x0.z; v[3] = x0.w;
                v[4] = x1.x; v[5] = x1.y; v[6] = x1.z; v[7] = x1.w;
            } else {
                #pragma unroll
                for (int j = 0; j < 8; j++) v[j] = 0.f;
            }
            uint4 hi, lo;
            split2(v[0], v[1], hi.x, lo.x);
            split2(v[2], v[3], hi.y, lo.y);
            split2(v[4], v[5], hi.z, lo.z);
            split2(v[6], v[7], hi.w, lo.w);
            uint32_t off = img_off(rr, seg);
            *(uint4*)(g_ft_hi + (size_t)bi * 32768 + off) = hi;
            *(uint4*)(g_ft_lo + (size_t)bi * 32768 + off) = lo;
        }
    } else {
        int r = bi - N_TILES;
        const float* Wr = W + (size_t)r * D * D;
        int n = t & 127;
        #pragma unroll
        for (int i = 0; i < 8; i++) {
            int seg = (t >> 7) + 2 * i;
            float v[8];
            #pragma unroll
            for (int j = 0; j < 8; j++)
                v[j] = Wr[(seg * 8 + j) * D + n];
            uint4 hi, lo;
            split2(v[0], v[1], hi.x, lo.x);
            split2(v[2], v[3], hi.y, lo.y);
            split2(v[4], v[5], hi.z, lo.z);
            split2(v[6], v[7], hi.w, lo.w);
            uint32_t off = img_off(n, seg);
            *(uint4*)(g_wt_hi + r * 32768 + off) = hi;
            *(uint4*)(g_wt_lo + r * 32768 + off) = lo;
        }
    }
}

// -------- kernel 2: init (out = sum_r b_r; zero degrees + hist) ------------
__global__ void init_kernel(const float* __restrict__ b, float* __restrict__ out) {
    int i = blockIdx.x * blockDim.x + threadIdx.x;
    if (i < N_NODES * D / 4) {
        int c = (i & 31) * 4;
        float4 v = make_float4(0.f, 0.f, 0.f, 0.f);
        #pragma unroll
        for (int r = 0; r < N_REL; r++) {
            v.x += b[r * D + c];     v.y += b[r * D + c + 1];
            v.z += b[r * D + c + 2]; v.w += b[r * D + c + 3];
        }
        ((float4*)out)[i] = v;
    }
    if (i < NTOT / 4) {
        float4 z = make_float4(0.f, 0.f, 0.f, 0.f);
        ((float4*)g_odeg)[i] = z;
        ((float4*)g_ideg)[i] = z;
    }
    if (i < NBINS) g_hist[i] = 0;
}

// -------- kernel 3: degrees + src-tile histogram ----------------------------
__global__ void degree_kernel(const int* __restrict__ src,
                              const int* __restrict__ dst) {
    int e = blockIdx.x * blockDim.x + threadIdx.x;
    int r = blockIdx.y;
    if (e < N_EDGES) {
        int s = src[r * N_EDGES + e];
        int d = dst[r * N_EDGES + e];
        atomicAdd(&g_odeg[r * N_NODES + s], 1.0f);
        atomicAdd(&g_ideg[r * N_NODES + d], 1.0f);
        atomicAdd(&g_hist[r * N_TILES + (s >> 7)], 1);
    }
}

// -------- kernel 4: exclusive scan of 3128 bins (single block) --------------
__global__ void scan_kernel() {
    __shared__ int warp_sums[32];
    int t = threadIdx.x;                  // 1024 threads
    int lane = t & 31, wid = t >> 5;
    int base = t * 4;
    int v[4], s = 0;
    #pragma unroll
    for (int j = 0; j < 4; j++) {
        v[j] = (base + j < NBINS) ? g_hist[base + j] : 0;
        s += v[j];
    }
    int x = s;
    #pragma unroll
    for (int o = 1; o < 32; o <<= 1) {
        int y = __shfl_up_sync(0xFFFFFFFF, x, o);
        if (lane >= o) x += y;
    }
    if (lane == 31) warp_sums[wid] = x;
    __syncthreads();
    if (wid == 0) {
        int y = warp_sums[lane];
        #pragma unroll
        for (int o = 1; o < 32; o <<= 1) {
            int z = __shfl_up_sync(0xFFFFFFFF, y, o);
            if (lane >= o) y += z;
        }
        warp_sums[lane] = y;
    }
    __syncthreads();
    int run = x - s + (wid > 0 ? warp_sums[wid - 1] : 0);   // exclusive prefix
    #pragma unroll
    for (int j = 0; j < 4; j++) {
        if (base + j < NBINS) {
            g_off[base + j] = run;
            g_cur[base + j] = run;
        }
        run += v[j];
    }
    if (t == 1023) g_off[NBINS] = run;    // total = 512000
}

// -------- kernel 5: fill sorted edge records --------------------------------
__global__ void fill_kernel(const int* __restrict__ src,
                            const int* __restrict__ dst) {
    int e = blockIdx.x * blockDim.x + threadIdx.x;
    int r = blockIdx.y;
    if (e >= N_EDGES) return;
    int s = src[r * N_EDGES + e];
    int d = dst[r * N_EDGES + e];
    float sc = rsqrtf(fmaxf(g_odeg[r * N_NODES + s], 1.0f))
             * rsqrtf(fmaxf(g_ideg[r * N_NODES + d], 1.0f));
    int bin = r * N_TILES + (s >> 7);
    int pos = atomicAdd(&g_cur[bin], 1);
    g_edges[pos] = make_uint2((uint32_t)(s & 127) | ((uint32_t)d << 7),
                              __float_as_uint(sc));
}

// -------- kernel 6: fused GEMM + edge scatter -------------------------------
#define OFF_A_HI  0
#define OFF_A_LO  32768
#define OFF_W_HI  65536
#define OFF_W_LO  98304
#define OFF_Y     131072
#define YSTRIDE   132                 // floats; 528 B rows, 16B-aligned, no LDS conflicts
#define GEMM_SMEM (131072 + 128 * YSTRIDE * 4)   // 198656 B

__global__ void __launch_bounds__(256, 1)
gemm_fused_kernel(float* __restrict__ out) {
    extern __shared__ char smem[];
    uint32_t sb = smem_u32(smem);
    float* Ysm = (float*)(smem + OFF_Y);
    int t = threadIdx.x, wid = t >> 5, lane = t & 31;
    int ti = blockIdx.x;
    int row0 = ti * 128;

    int mw0 = (wid >> 2) * 64;
    int nw0 = (wid & 3) * 32;
    int lrow = lane & 15;
    int ksel = lane >> 4;

    // stage A + W_0 (one group)
    {
        const uint8_t* ah = g_ft_hi + (size_t)ti * 32768;
        const uint8_t* al = g_ft_lo + (size_t)ti * 32768;
        #pragma unroll
        for (int i = 0; i < 8; i++) {
            uint32_t o = (uint32_t)(t + 256 * i) * 16;
            cp_async16(sb + OFF_A_HI + o, ah + o);
            cp_async16(sb + OFF_A_LO + o, al + o);
            cp_async16(sb + OFF_W_HI + o, g_wt_hi + o);
            cp_async16(sb + OFF_W_LO + o, g_wt_lo + o);
        }
    }
    CP_COMMIT();
    CP_WAIT(0);
    __syncthreads();

    for (int r = 0; r < N_REL; r++) {
        // ---- MMA phase ----
        float acc[4][4][4];
        #pragma unroll
        for (int mi = 0; mi < 4; mi++)
            #pragma unroll
            for (int ni = 0; ni < 4; ni++)
                #pragma unroll
                for (int q = 0; q < 4; q++) acc[mi][ni][q] = 0.f;

        #pragma unroll
        for (int ks = 0; ks < 8; ks++) {
            int kc = ks * 2 + ksel;
            uint32_t ah[4][4], al[4][4];
            #pragma unroll
            for (int mi = 0; mi < 4; mi++) {
                uint32_t off = img_off(mw0 + mi * 16 + lrow, kc);
                ldsm_x4(sb + OFF_A_HI + off, ah[mi][0], ah[mi][1], ah[mi][2], ah[mi][3]);
                ldsm_x4(sb + OFF_A_LO + off, al[mi][0], al[mi][1], al[mi][2], al[mi][3]);
            }
            uint32_t bh[4][2], bl[4][2];
            #pragma unroll
            for (int nh = 0; nh < 2; nh++) {
                uint32_t off = img_off(nw0 + nh * 16 + lrow, kc);
                uint32_t r0, r1, r2, r3;
                ldsm_x4(sb + OFF_W_HI + off, r0, r1, r2, r3);
                bh[2 * nh][0] = r0; bh[2 * nh + 1][0] = r1;
                bh[2 * nh][1] = r2; bh[2 * nh + 1][1] = r3;
                ldsm_x4(sb + OFF_W_LO + off, r0, r1, r2, r3);
                bl[2 * nh][0] = r0; bl[2 * nh + 1][0] = r1;
                bl[2 * nh][1] = r2; bl[2 * nh + 1][1] = r3;
            }
            #pragma unroll
            for (int mi = 0; mi < 4; mi++)
                #pragma unroll
                for (int ni = 0; ni < 4; ni++) {
                    float* d = acc[mi][ni];
                    mma_bf16(d[0], d[1], d[2], d[3],
                             ah[mi][0], ah[mi][1], ah[mi][2], ah[mi][3],
                             bh[ni][0], bh[ni][1]);
                    mma_bf16(d[0], d[1], d[2], d[3],
                             ah[mi][0], ah[mi][1], ah[mi][2], ah[mi][3],
                             bl[ni][0], bl[ni][1]);
                    mma_bf16(d[0], d[1], d[2], d[3],
                             al[mi][0], al[mi][1], al[mi][2], al[mi][3],
                             bh[ni][0], bh[ni][1]);
                }
        }
        __syncthreads();                 // all warps done reading W

        // ---- prefetch W_{r+1} into the (now dead) W buffer ----
        if (r + 1 < N_REL) {
            const uint8_t* wh = g_wt_hi + (r + 1) * 32768;
            const uint8_t* wl = g_wt_lo + (r + 1) * 32768;
            #pragma unroll
            for (int i = 0; i < 8; i++) {
                uint32_t o = (uint32_t)(t + 256 * i) * 16;
                cp_async16(sb + OFF_W_HI + o, wh + o);
                cp_async16(sb + OFF_W_LO + o, wl + o);
            }
            CP_COMMIT();
        }

        // ---- write Y tile to smem ----
        {
            int qr = lane >> 2;
            int qc = (lane & 3) * 2;
            #pragma unroll
            for (int mi = 0; mi < 4; mi++)
                #pragma unroll
                for (int ni = 0; ni < 4; ni++) {
                    int c  = nw0 + ni * 8 + qc;
                    int ra = mw0 + mi * 16 + qr;
                    *(float2*)(Ysm + ra * YSTRIDE + c) =
                        make_float2(acc[mi][ni][0], acc[mi][ni][1]);
                    *(float2*)(Ysm + (ra + 8) * YSTRIDE + c) =
                        make_float2(acc[mi][ni][2], acc[mi][ni][3]);
                }
        }
        __syncthreads();                 // Y visible to all warps

        // ---- edge phase: scatter this tile's edges for relation r ----
        {
            int bin   = r * N_TILES + ti;
            int start = g_off[bin];
            int end   = g_off[bin + 1];
            for (int i = start + wid; i < end; i += 8) {
                uint2 ed = g_edges[i];
                int   sl = ed.x & 127;
                int   d  = ed.x >> 7;
                float sc = __uint_as_float(ed.y);
                float4 v = *(float4*)(Ysm + sl * YSTRIDE + lane * 4);
                v.x *= sc; v.y *= sc; v.z *= sc; v.w *= sc;
                red_add_v4(&out[(size_t)d * D + lane * 4], v);
            }
        }
        CP_WAIT(0);
        __syncthreads();                 // W_{r+1} ready; Y safe to overwrite
    }
}

// -------- launch -----------------------------------------------------------
extern "C" void kernel_launch(void* const* d_in, const int* in_sizes, int n_in,
                              void* d_out, int out_size) {
    const float* feat = (const float*)d_in[0];   // [50000,128] f32
    const float* W    = (const float*)d_in[1];   // [8,128,128] f32
    const float* b    = (const float*)d_in[2];   // [8,128]     f32
    const int*   src  = (const int*)d_in[3];     // [8,64000]   int32
    const int*   dst  = (const int*)d_in[4];     // [8,64000]   int32
    float* out = (float*)d_out;                  // [50000,128] f32

    cudaFuncSetAttribute(gemm_fused_kernel,
                         cudaFuncAttributeMaxDynamicSharedMemorySize, GEMM_SMEM);

    prep_kernel<<<N_TILES + N_REL, 256>>>(feat, W);          // 1
    init_kernel<<<(N_NODES * D / 4 + 255) / 256, 256>>>(b, out);  // 2
    dim3 egrid(N_EDGES / 256, N_REL);
    degree_kernel<<<egrid, 256>>>(src, dst);                 // 3
    scan_kernel<<<1, 1024>>>();                              // 4
    fill_kernel<<<egrid, 256>>>(src, dst);                   // 5
    gemm_fused_kernel<<<N_TILES, 256, GEMM_SMEM>>>(out);     // 6 (profiled)
}